// round 14
// baseline (speedup 1.0000x reference)
#include <cuda_runtime.h>
#include <cuda_fp16.h>
#include <cstdint>
#include <math.h>

// ---------------- problem constants ----------------
#define NPATCH 500
#define DMODEL 512
#define KDIM   32
#define QKVD   160
#define FFD    2048
#define NLAYER 6
#define NBATCH 32
#define NCLS   256
#define LN_EPS 1e-3f
#define RTOT 875
#define NBLK 148

// fp16 GEMM smem layout (halves): A: [s*2560 + m*40 + k], B: [7680 + s*2560 + n*40 + k]
#define AST 2560
#define BBASE 7680
#define DSMEM 46080   // bytes: max(gemm 30720, attn 43520) + pad

// ---------------- scratch ----------------
__device__ float  d_h   [NPATCH * DMODEL];
__device__ __half d_h16 [NPATCH * DMODEL];
__device__ __half d_pool16[375 * DMODEL];
__device__ float  d_q   [RTOT * QKVD];
__device__ float  d_k   [RTOT * QKVD];
__device__ float  d_v   [RTOT * QKVD];
__device__ __half d_o16 [RTOT * QKVD];
__device__ __half d_ao16[RTOT * DMODEL];
__device__ __half d_ff16[NPATCH * FFD];
__device__ float  d_part[4 * NPATCH * DMODEL];
__device__ float  d_cs  [DMODEL];
__device__ __half d_Wq16[18 * QKVD * DMODEL];
__device__ __half d_Wk16[18 * QKVD * DMODEL];
__device__ __half d_Wv16[18 * QKVD * DMODEL];
__device__ __half d_Wo16[18 * DMODEL * QKVD];
__device__ __half d_Wc16[18 * DMODEL * DMODEL];
__device__ __half d_W116[6 * FFD * DMODEL];
__device__ __half d_W216[6 * DMODEL * FFD];

// grid barrier state
__device__ volatile unsigned g_cnt;
__device__ volatile unsigned g_gen;

// ---------------- helpers ----------------
__device__ __forceinline__ uint32_t smem_u32(const void* p) {
    return (uint32_t)__cvta_generic_to_shared(p);
}
__device__ __forceinline__ void cp16(uint32_t dst, const void* src) {
    asm volatile("cp.async.cg.shared.global [%0], [%1], 16;\n" :: "r"(dst), "l"(src));
}
__device__ __forceinline__ void cp_commit() { asm volatile("cp.async.commit_group;\n"); }
__device__ __forceinline__ void ldsm4(uint32_t& d0, uint32_t& d1, uint32_t& d2, uint32_t& d3,
                                      uint32_t addr) {
    asm volatile("ldmatrix.sync.aligned.m8n8.x4.shared.b16 {%0,%1,%2,%3}, [%4];"
                 : "=r"(d0), "=r"(d1), "=r"(d2), "=r"(d3) : "r"(addr));
}
__device__ __forceinline__ void mma_f16(float* c, const uint32_t* a, uint32_t b0, uint32_t b1) {
    asm volatile(
        "mma.sync.aligned.m16n8k16.row.col.f32.f16.f16.f32 "
        "{%0,%1,%2,%3}, {%4,%5,%6,%7}, {%8,%9}, {%0,%1,%2,%3};"
        : "+f"(c[0]), "+f"(c[1]), "+f"(c[2]), "+f"(c[3])
        : "r"(a[0]), "r"(a[1]), "r"(a[2]), "r"(a[3]), "r"(b0), "r"(b1));
}
__device__ __forceinline__ float gelu_f(float x) {
    return 0.5f * x * (1.f + erff(x * 0.70710678118654752f));
}

// two-phase software grid barrier (all NBLK CTAs co-resident)
__device__ __forceinline__ void gsync() {
    __syncthreads();
    if (threadIdx.x == 0) {
        unsigned gen = g_gen;
        __threadfence();
        unsigned t = atomicAdd((unsigned*)&g_cnt, 1u);
        if (t == (unsigned)gridDim.x - 1u) {
            g_cnt = 0;
            __threadfence();
            g_gen = gen + 1u;
        } else {
            while (g_gen == gen) {}
        }
        __threadfence();
    }
    __syncthreads();
}

// ---------------- transpose + convert (preamble launches) ----------------
__global__ void transconv(const float* __restrict__ src, __half* __restrict__ dst,
                          int K, int N) {
    __shared__ float tile[32][33];
    const size_t b = blockIdx.z;
    src += b * (size_t)K * N;
    dst += b * (size_t)N * K;
    int n0 = blockIdx.x * 32, k0 = blockIdx.y * 32;
    int tx = threadIdx.x, ty = threadIdx.y;   // 32 x 8
    #pragma unroll
    for (int i = 0; i < 32; i += 8)
        tile[ty + i][tx] = src[(size_t)(k0 + ty + i) * N + n0 + tx];
    __syncthreads();
    #pragma unroll
    for (int i = 0; i < 32; i += 8)
        dst[(size_t)(n0 + ty + i) * K + k0 + tx] = __float2half_rn(tile[tx][ty + i]);
}

// ---------------- fp16 GEMM tile (noinline; dynamic smem) ----------------
__device__ __noinline__ void gemm_core(
    const __half* __restrict__ A, const __half* __restrict__ Bt,
    const float* __restrict__ bias, float* __restrict__ C, __half* __restrict__ C16,
    int M, int N, int lda, int ldb, int kOff, int kLen,
    int bM, int bN, int act, int addBias, int ldc)
{
    extern __shared__ __half smh[];
    __syncthreads();   // protect smem reuse across back-to-back tiles / stages

    const int tid = threadIdx.x, lane = tid & 31, warp = tid >> 5;
    const int wm = (warp & 1) << 5;
    const int wn = (warp >> 1) << 4;
    const int g = lane >> 2, t = lane & 3;
    const int lrow = (lane & 7) + ((lane >> 3) & 1) * 8;
    const int lk8 = (lane >> 4) << 3;

    const int frow = tid >> 2;
    const int fch = (tid & 3) << 3;
    const __half* aSrc = A + (size_t)min(bM + frow, M - 1) * lda + kOff + fch;
    const __half* bSrc = Bt + (size_t)min(bN + frow, N - 1) * ldb + kOff + fch;
    uint32_t aD[3], bD[3];
    #pragma unroll
    for (int s = 0; s < 3; ++s) {
        aD[s] = smem_u32(&smh[s * AST + frow * 40 + fch]);
        bD[s] = smem_u32(&smh[BBASE + s * AST + frow * 40 + fch]);
    }

    const int T = kLen >> 5;
    #pragma unroll
    for (int p = 0; p < 2; ++p) {
        cp16(aD[p], aSrc + (p << 5));
        cp16(bD[p], bSrc + (p << 5));
        cp_commit();
    }

    const uint32_t smb = smem_u32(smh);
    uint32_t aFrag[2];
    #pragma unroll
    for (int i = 0; i < 2; ++i)
        aFrag[i] = ((wm + i * 16 + lrow) * 40 + lk8) * 2;
    const uint32_t bFrag = (BBASE + (wn + lrow) * 40 + lk8) * 2;

    float acc[2][2][4] = {};
    int stage = 0;
    for (int tt = 0; tt < T; ++tt) {
        if (tt + 1 < T) { asm volatile("cp.async.wait_group 1;\n"); }
        else            { asm volatile("cp.async.wait_group 0;\n"); }
        __syncthreads();

        if (tt + 2 < T) {
            const int ns = (stage + 2 >= 3) ? stage - 1 : stage + 2;
            const int ko = (tt + 2) << 5;
            cp16(aD[ns], aSrc + ko);
            cp16(bD[ns], bSrc + ko);
            cp_commit();
        }

        const uint32_t sb = smb + stage * (AST * 2);
        #pragma unroll
        for (int ks = 0; ks < 2; ++ks) {
            uint32_t af[2][4], bf[4];
            ldsm4(af[0][0], af[0][1], af[0][2], af[0][3], sb + aFrag[0] + ks * 32);
            ldsm4(af[1][0], af[1][1], af[1][2], af[1][3], sb + aFrag[1] + ks * 32);
            ldsm4(bf[0], bf[1], bf[2], bf[3], sb + bFrag + ks * 32);
            mma_f16(acc[0][0], af[0], bf[0], bf[2]);
            mma_f16(acc[0][1], af[0], bf[1], bf[3]);
            mma_f16(acc[1][0], af[1], bf[0], bf[2]);
            mma_f16(acc[1][1], af[1], bf[1], bf[3]);
        }
        stage = (stage + 1 >= 3) ? 0 : stage + 1;
    }

    #pragma unroll
    for (int i = 0; i < 2; ++i) {
        const int r0 = bM + wm + (i << 4) + g;
        const int r1 = r0 + 8;
        #pragma unroll
        for (int j = 0; j < 2; ++j) {
            const int col = bN + wn + (j << 3) + (t << 1);
            if (col >= N) continue;
            float b0v = 0.f, b1v = 0.f;
            if (addBias) {
                float2 bb = *(const float2*)(bias + col);
                b0v = bb.x; b1v = bb.y;
            }
            float c0 = acc[i][j][0] + b0v, c1 = acc[i][j][1] + b1v;
            float c2 = acc[i][j][2] + b0v, c3 = acc[i][j][3] + b1v;
            if (act) { c0 = gelu_f(c0); c1 = gelu_f(c1); c2 = gelu_f(c2); c3 = gelu_f(c3); }
            if (C16) {
                if (r0 < M) {
                    C16[(size_t)r0 * ldc + col] = __float2half_rn(c0);
                    C16[(size_t)r0 * ldc + col + 1] = __float2half_rn(c1);
                }
                if (r1 < M) {
                    C16[(size_t)r1 * ldc + col] = __float2half_rn(c2);
                    C16[(size_t)r1 * ldc + col + 1] = __float2half_rn(c3);
                }
            } else {
                if (r0 < M) *(float2*)(C + (size_t)r0 * ldc + col) = make_float2(c0, c1);
                if (r1 < M) *(float2*)(C + (size_t)r1 * ldc + col) = make_float2(c2, c3);
            }
        }
    }
}

// ---------------- attention unit (one (scale,head,8q) block) ----------------
__device__ __noinline__ void attn_unit(int b, const float* __restrict__ q,
                                       const float* __restrict__ k,
                                       const float* __restrict__ v,
                                       __half* __restrict__ o16)
{
    extern __shared__ char smraw[];
    float (*Ks)[34] = (float(*)[34])smraw;
    float (*Vs)[34] = (float(*)[34])(smraw + 4352);
    float (*OS)[32][34] = (float(*)[32][34])(smraw + 8704);

    __syncthreads();   // protect smem reuse

    int Ns, ro, h, qg;
    if (b < 315)      { Ns = 500; ro = 0;   h = b / 63;  qg = b % 63; }
    else if (b < 475) { int c = b - 315; Ns = 250; ro = 500; h = c / 32; qg = c % 32; }
    else              { int c = b - 475; Ns = 125; ro = 750; h = c / 16; qg = c % 16; }

    const int wid = threadIdx.x >> 5;
    const int lane = threadIdx.x & 31;
    const int n = qg * 8 + wid;
    const bool valid = n < Ns;
    const int nq = valid ? n : (Ns - 1);
    const float scale = 0.1767766952966369f;

    float2 qr[16];
    {
        const float2* qp = (const float2*)(q + (size_t)(ro + nq) * QKVD + h * KDIM);
        #pragma unroll
        for (int i = 0; i < 16; i++) {
            float2 tq = qp[i];
            qr[i] = make_float2(tq.x * scale, tq.y * scale);
        }
    }

    float mmax = -INFINITY, ssum = 0.f;
    float oa[32];
    #pragma unroll
    for (int d = 0; d < 32; d++) oa[d] = 0.f;

    const int nt = (Ns + 31) >> 5;
    for (int tt = 0; tt < nt; tt++) {
        const int kt = tt << 5;
        {
            const int m = threadIdx.x >> 3;
            const int dq = (threadIdx.x & 7) << 2;
            const int row = min(kt + m, Ns - 1);
            const float4 kk = *(const float4*)(k + (size_t)(ro + row) * QKVD + h * KDIM + dq);
            const float4 vv = *(const float4*)(v + (size_t)(ro + row) * QKVD + h * KDIM + dq);
            *(float2*)&Ks[m][dq]     = make_float2(kk.x, kk.y);
            *(float2*)&Ks[m][dq + 2] = make_float2(kk.z, kk.w);
            *(float2*)&Vs[m][dq]     = make_float2(vv.x, vv.y);
            *(float2*)&Vs[m][dq + 2] = make_float2(vv.z, vv.w);
        }
        __syncthreads();

        float s0 = 0.f, s1 = 0.f;
        #pragma unroll
        for (int i = 0; i < 16; i++) {
            float2 kk = *(const float2*)&Ks[lane][2 * i];
            s0 = fmaf(qr[i].x, kk.x, s0);
            s1 = fmaf(qr[i].y, kk.y, s1);
        }
        float s = s0 + s1;
        if (kt + lane >= Ns) s = -INFINITY;

        float nm = fmaxf(mmax, s);
        float corr = __expf(mmax - nm);
        float p = __expf(s - nm);
        ssum = ssum * corr + p;
        #pragma unroll
        for (int i = 0; i < 16; i++) {
            float2 vv = *(const float2*)&Vs[lane][2 * i];
            oa[2 * i]     = oa[2 * i]     * corr + p * vv.x;
            oa[2 * i + 1] = oa[2 * i + 1] * corr + p * vv.y;
        }
        mmax = nm;
        __syncthreads();
    }

    float gm = mmax;
    #pragma unroll
    for (int off = 16; off; off >>= 1) gm = fmaxf(gm, __shfl_xor_sync(0xffffffffu, gm, off));
    float c = __expf(mmax - gm);
    float ss = ssum * c;
    #pragma unroll
    for (int off = 16; off; off >>= 1) ss += __shfl_xor_sync(0xffffffffu, ss, off);

    #pragma unroll
    for (int i = 0; i < 16; i++)
        *(float2*)&OS[wid][lane][2 * i] = make_float2(oa[2 * i] * c, oa[2 * i + 1] * c);
    __syncwarp();

    float accd = 0.f;
    #pragma unroll
    for (int m = 0; m < 32; m++) accd += OS[wid][m][lane];
    if (valid)
        o16[(size_t)(ro + n) * QKVD + h * KDIM + lane] = __float2half_rn(accd / ss);
}

// ---------------- LN row helpers ----------------
__device__ __forceinline__ void ln_finish(float v0, float v1, int n, int t,
                                          float* red, float* statp,
                                          float* __restrict__ h, __half* __restrict__ h16,
                                          const float* __restrict__ g,
                                          const float* __restrict__ b) {
    float s = v0 + v1;
    #pragma unroll
    for (int o = 16; o; o >>= 1) s += __shfl_xor_sync(0xffffffffu, s, o);
    if ((t & 31) == 0) red[t >> 5] = s;
    __syncthreads();
    if (t < 32) {
        float x = (t < 8) ? red[t] : 0.f;
        #pragma unroll
        for (int o = 4; o; o >>= 1) x += __shfl_xor_sync(0xffffffffu, x, o);
        if (t == 0) *statp = x / (float)DMODEL;
    }
    __syncthreads();
    float mean = *statp;
    float dd0 = v0 - mean, dd1 = v1 - mean;
    __syncthreads();
    float vs = dd0 * dd0 + dd1 * dd1;
    #pragma unroll
    for (int o = 16; o; o >>= 1) vs += __shfl_xor_sync(0xffffffffu, vs, o);
    if ((t & 31) == 0) red[t >> 5] = vs;
    __syncthreads();
    if (t < 32) {
        float x = (t < 8) ? red[t] : 0.f;
        #pragma unroll
        for (int o = 4; o; o >>= 1) x += __shfl_xor_sync(0xffffffffu, x, o);
        if (t == 0) *statp = rsqrtf(x / (float)DMODEL + LN_EPS);
    }
    __syncthreads();
    float rstd = *statp;
    float o0 = dd0 * rstd * g[t] + b[t];
    float o1 = dd1 * rstd * g[t + 256] + b[t + 256];
    h[n * DMODEL + t] = o0;
    h[n * DMODEL + t + 256] = o1;
    h16[n * DMODEL + t] = __float2half_rn(o0);
    h16[n * DMODEL + t + 256] = __float2half_rn(o1);
}

__device__ __noinline__ void ln_row_comb(int n, const float* __restrict__ P,
                                         const float* __restrict__ bias,
                                         float* __restrict__ h, __half* __restrict__ h16,
                                         const float* __restrict__ g,
                                         const float* __restrict__ b) {
    __shared__ float red[8];
    __shared__ float stat;
    int t = threadIdx.x;
    const size_t ND = (size_t)NPATCH * DMODEL;
    const int n2 = n >> 1, n4 = n >> 2;
    float v0 = h[n * DMODEL + t]       + bias[t];
    float v1 = h[n * DMODEL + t + 256] + bias[t + 256];
    v0 += P[0 * ND + (size_t)n  * DMODEL + t];
    v1 += P[0 * ND + (size_t)n  * DMODEL + t + 256];
    v0 += P[1 * ND + (size_t)n2 * DMODEL + t];
    v1 += P[1 * ND + (size_t)n2 * DMODEL + t + 256];
    v0 += P[2 * ND + (size_t)n4 * DMODEL + t];
    v1 += P[2 * ND + (size_t)n4 * DMODEL + t + 256];
    ln_finish(v0, v1, n, t, red, &stat, h, h16, g, b);
}

__device__ __noinline__ void ln_row_ffn(int n, const float* __restrict__ P,
                                        const float* __restrict__ bias,
                                        float* __restrict__ h, __half* __restrict__ h16,
                                        const float* __restrict__ g,
                                        const float* __restrict__ b) {
    __shared__ float red[8];
    __shared__ float stat;
    int t = threadIdx.x;
    float v0 = h[n * DMODEL + t]       + bias[t];
    float v1 = h[n * DMODEL + t + 256] + bias[t + 256];
    #pragma unroll
    for (int s = 0; s < 4; s++) {
        v0 += P[(size_t)s * NPATCH * DMODEL + n * DMODEL + t];
        v1 += P[(size_t)s * NPATCH * DMODEL + n * DMODEL + t + 256];
    }
    ln_finish(v0, v1, n, t, red, &stat, h, h16, g, b);
}

// ---------------- THE MEGAKERNEL: all 6 layers ----------------
__constant__ int c_Ms[3] = {500, 250, 125};
__constant__ int c_ro[3] = {0, 500, 750};

__global__ void __launch_bounds__(256) layers_kernel(
    const __half* __restrict__ wq16, const __half* __restrict__ wk16,
    const __half* __restrict__ wv16, const __half* __restrict__ wo16,
    const __half* __restrict__ wc16, const __half* __restrict__ w116,
    const __half* __restrict__ w216,
    const float* __restrict__ bq, const float* __restrict__ bk,
    const float* __restrict__ bv, const float* __restrict__ bo,
    const float* __restrict__ bc, const float* __restrict__ b1,
    const float* __restrict__ b2,
    const float* __restrict__ ln1_g, const float* __restrict__ ln1_b,
    const float* __restrict__ ln2_g, const float* __restrict__ ln2_b,
    float* __restrict__ h, __half* __restrict__ h16, __half* __restrict__ pool16,
    float* __restrict__ q, float* __restrict__ k, float* __restrict__ v,
    __half* __restrict__ o16, __half* __restrict__ ao16, __half* __restrict__ ff16,
    float* __restrict__ part)
{
    const int bid = blockIdx.x;
    const int tid = threadIdx.x;

    for (int l = 0; l < NLAYER; l++) {
        const __half* Wq = wq16 + (size_t)l * 3 * QKVD * DMODEL;
        const __half* Wk = wk16 + (size_t)l * 3 * QKVD * DMODEL;
        const __half* Wv = wv16 + (size_t)l * 3 * QKVD * DMODEL;
        const __half* Wo = wo16 + (size_t)l * 3 * DMODEL * QKVD;
        const __half* Wc = wc16 + (size_t)l * 3 * DMODEL * DMODEL;
        const __half* W1 = w116 + (size_t)l * FFD * DMODEL;
        const __half* W2 = w216 + (size_t)l * DMODEL * FFD;
        const float* lbq = bq + (size_t)l * 3 * QKVD;
        const float* lbk = bk + (size_t)l * 3 * QKVD;
        const float* lbv = bv + (size_t)l * 3 * QKVD;
        const float* lbo = bo + (size_t)l * 3 * DMODEL;

        // stage A: pool (375 x 512)
        for (int i = bid * 256 + tid; i < 375 * DMODEL; i += NBLK * 256) {
            int r = i >> 9, d = i & 511;
            float val;
            if (r < 250) {
                val = 0.5f * (h[(2 * r) * DMODEL + d] + h[(2 * r + 1) * DMODEL + d]);
            } else {
                int j = r - 250;
                val = 0.25f * (h[(4 * j) * DMODEL + d] + h[(4 * j + 1) * DMODEL + d] +
                               h[(4 * j + 2) * DMODEL + d] + h[(4 * j + 3) * DMODEL + d]);
            }
            pool16[i] = __float2half_rn(val);
        }
        gsync();

        // stage B: qkv — 126 tiles
        for (int tt = bid; tt < 126; tt += NBLK) {
            int r = tt, si, which, my, nx;
            if (r < 72)       { si = 0; which = r / 24; r %= 24; my = r / 3; nx = r % 3; }
            else if (r < 108) { r -= 72; si = 1; which = r / 12; r %= 12; my = r / 3; nx = r % 3; }
            else              { r -= 108; si = 2; which = r / 6; r %= 6; my = r / 3; nx = r % 3; }
            int M = c_Ms[si];
            const __half* A = (si == 0) ? h16 : (pool16 + (si == 2 ? 250 * DMODEL : 0));
            const __half* W = (which == 0) ? Wq : (which == 1) ? Wk : Wv;
            const float* bb = (which == 0) ? lbq : (which == 1) ? lbk : lbv;
            float* Cb = (which == 0) ? q : (which == 1) ? k : v;
            gemm_core(A, W + (size_t)si * QKVD * DMODEL, bb + (size_t)si * QKVD,
                      Cb + (size_t)c_ro[si] * QKVD, nullptr,
                      M, QKVD, DMODEL, DMODEL, 0, DMODEL, my * 64, nx * 64, 0, 1, QKVD);
        }
        gsync();

        // stage C: attention — 555 units
        for (int u = bid; u < 555; u += NBLK)
            attn_unit(u, q, k, v, o16);
        gsync();

        // stage D: wo — 112 tiles (fp16 out, fused bias)
        for (int tt = bid; tt < 112; tt += NBLK) {
            int r = tt, si, my, nx;
            if (r < 64)      { si = 0; my = r >> 3; nx = r & 7; }
            else if (r < 96) { r -= 64; si = 1; my = r >> 3; nx = r & 7; }
            else             { r -= 96; si = 2; my = r >> 3; nx = r & 7; }
            int M = c_Ms[si];
            gemm_core(o16 + (size_t)c_ro[si] * QKVD, Wo + (size_t)si * DMODEL * QKVD,
                      lbo + (size_t)si * DMODEL, nullptr, ao16 + (size_t)c_ro[si] * DMODEL,
                      M, DMODEL, QKVD, QKVD, 0, QKVD, my * 64, nx * 64, 0, 1, DMODEL);
        }
        gsync();

        // stage E: comb — 112 tiles (fp32 partials per scale)
        for (int tt = bid; tt < 112; tt += NBLK) {
            int r = tt, si, my, nx;
            if (r < 64)      { si = 0; my = r >> 3; nx = r & 7; }
            else if (r < 96) { r -= 64; si = 1; my = r >> 3; nx = r & 7; }
            else             { r -= 96; si = 2; my = r >> 3; nx = r & 7; }
            int M = c_Ms[si];
            gemm_core(ao16 + (size_t)c_ro[si] * DMODEL, Wc + (size_t)si * DMODEL * DMODEL,
                      nullptr, part + (size_t)si * NPATCH * DMODEL, nullptr,
                      M, DMODEL, DMODEL, DMODEL, 0, DMODEL, my * 64, nx * 64, 0, 0, DMODEL);
        }
        gsync();

        // stage F: LN1 — 500 rows
        for (int n = bid; n < NPATCH; n += NBLK)
            ln_row_comb(n, part, bc + (size_t)l * DMODEL, h, h16,
                        ln1_g + (size_t)l * DMODEL, ln1_b + (size_t)l * DMODEL);
        gsync();

        // stage G: ffn1 — 256 tiles (gelu, fp16 out)
        for (int tt = bid; tt < 256; tt += NBLK) {
            int my = tt >> 5, nx = tt & 31;
            gemm_core(h16, W1, b1 + (size_t)l * FFD, nullptr, ff16,
                      NPATCH, FFD, DMODEL, DMODEL, 0, DMODEL, my * 64, nx * 64, 1, 1, FFD);
        }
        gsync();

        // stage H: ffn2 split-K4 — 256 tiles
        for (int tt = bid; tt < 256; tt += NBLK) {
            int z = tt >> 6, rr = tt & 63;
            int my = rr >> 3, nx = rr & 7;
            gemm_core(ff16, W2, nullptr, part + (size_t)z * NPATCH * DMODEL, nullptr,
                      NPATCH, DMODEL, FFD, FFD, z * 512, 512, my * 64, nx * 64, 0, 0, DMODEL);
        }
        gsync();

        // stage I: LN2 — 500 rows
        for (int n = bid; n < NPATCH; n += NBLK)
            ln_row_ffn(n, part, b2 + (size_t)l * DMODEL, h, h16,
                       ln2_g + (size_t)l * DMODEL, ln2_b + (size_t)l * DMODEL);
        gsync();
    }
}

// ---------------- small preamble kernels ----------------
__global__ void colsum_kernel(const float* __restrict__ W, float* __restrict__ cs) {
    int d = threadIdx.x;
    float s = 0.f;
    #pragma unroll 4
    for (int p = 0; p < 100; p++) s += W[p * DMODEL + d];
    cs[d] = s;
}

__global__ void init_h_kernel(const float* __restrict__ cs, const float* __restrict__ ln_in_b,
                              const float* __restrict__ patch_b, const float* __restrict__ pos,
                              float* __restrict__ h, __half* __restrict__ h16) {
    int n = blockIdx.x, d = threadIdx.x;
    float v = ln_in_b[0] * cs[d] + patch_b[d] + pos[n * DMODEL + d];
    h[n * DMODEL + d] = v;
    h16[n * DMODEL + d] = __float2half_rn(v);
}

// fused global-mean-pool + head + softmax + broadcast
__global__ void head_kernel(const float* __restrict__ h, const float* __restrict__ W,
                            const float* __restrict__ b, float* __restrict__ out) {
    __shared__ float gs[DMODEL];
    __shared__ float red[8];
    __shared__ float stat;
    int t = threadIdx.x;
    {
        float s0 = 0.f, s1 = 0.f;
        for (int n = 0; n < NPATCH; n++) {
            s0 += h[n * DMODEL + t];
            s1 += h[n * DMODEL + t + 256];
        }
        gs[t] = s0 / (float)NPATCH;
        gs[t + 256] = s1 / (float)NPATCH;
    }
    __syncthreads();
    float acc = b[t];
    #pragma unroll 4
    for (int d = 0; d < DMODEL; d++) acc += gs[d] * W[d * NCLS + t];

    float m = acc;
    #pragma unroll
    for (int o = 16; o; o >>= 1) m = fmaxf(m, __shfl_xor_sync(0xffffffffu, m, o));
    if ((t & 31) == 0) red[t >> 5] = m;
    __syncthreads();
    if (t < 32) {
        float x = (t < 8) ? red[t] : -INFINITY;
        #pragma unroll
        for (int o = 4; o; o >>= 1) x = fmaxf(x, __shfl_xor_sync(0xffffffffu, x, o));
        if (t == 0) stat = x;
    }
    __syncthreads();
    float e = expf(acc - stat);
    __syncthreads();
    float s = e;
    #pragma unroll
    for (int o = 16; o; o >>= 1) s += __shfl_xor_sync(0xffffffffu, s, o);
    if ((t & 31) == 0) red[t >> 5] = s;
    __syncthreads();
    if (t < 32) {
        float x = (t < 8) ? red[t] : 0.f;
        #pragma unroll
        for (int o = 4; o; o >>= 1) x += __shfl_xor_sync(0xffffffffu, x, o);
        if (t == 0) stat = x;
    }
    __syncthreads();
    float p = e / stat;
    for (int bb = 0; bb < NBATCH; bb++) out[bb * NCLS + t] = p;
}

// ---------------- host launcher ----------------
extern "C" void kernel_launch(void* const* d_in, const int* in_sizes, int n_in,
                              void* d_out, int out_size) {
    const float* ln_in_b = (const float*)d_in[2];
    const float* patch_W = (const float*)d_in[3];
    const float* patch_b = (const float*)d_in[4];
    const float* pos_emb = (const float*)d_in[5];
    const float* Wq = (const float*)d_in[6];
    const float* bq = (const float*)d_in[7];
    const float* Wk = (const float*)d_in[8];
    const float* bk = (const float*)d_in[9];
    const float* Wv = (const float*)d_in[10];
    const float* bv = (const float*)d_in[11];
    const float* Wo = (const float*)d_in[12];
    const float* bo = (const float*)d_in[13];
    const float* Wc = (const float*)d_in[14];
    const float* bc = (const float*)d_in[15];
    const float* ln1_g = (const float*)d_in[16];
    const float* ln1_b = (const float*)d_in[17];
    const float* W1 = (const float*)d_in[18];
    const float* b1 = (const float*)d_in[19];
    const float* W2 = (const float*)d_in[20];
    const float* b2 = (const float*)d_in[21];
    const float* ln2_g = (const float*)d_in[22];
    const float* ln2_b = (const float*)d_in[23];
    const float* head_W = (const float*)d_in[24];
    const float* head_b = (const float*)d_in[25];
    float* out = (float*)d_out;

    float *hp, *qp, *kp, *vp, *partp, *csp;
    __half *h16p, *pool16p, *o16p, *ao16p, *ff16p;
    __half *wq16, *wk16, *wv16, *wo16, *wc16, *w116, *w216;
    cudaGetSymbolAddress((void**)&hp,  d_h);
    cudaGetSymbolAddress((void**)&h16p, d_h16);
    cudaGetSymbolAddress((void**)&pool16p, d_pool16);
    cudaGetSymbolAddress((void**)&qp,  d_q);
    cudaGetSymbolAddress((void**)&kp,  d_k);
    cudaGetSymbolAddress((void**)&vp,  d_v);
    cudaGetSymbolAddress((void**)&o16p, d_o16);
    cudaGetSymbolAddress((void**)&ao16p, d_ao16);
    cudaGetSymbolAddress((void**)&ff16p, d_ff16);
    cudaGetSymbolAddress((void**)&partp, d_part);
    cudaGetSymbolAddress((void**)&csp, d_cs);
    cudaGetSymbolAddress((void**)&wq16, d_Wq16);
    cudaGetSymbolAddress((void**)&wk16, d_Wk16);
    cudaGetSymbolAddress((void**)&wv16, d_Wv16);
    cudaGetSymbolAddress((void**)&wo16, d_Wo16);
    cudaGetSymbolAddress((void**)&wc16, d_Wc16);
    cudaGetSymbolAddress((void**)&w116, d_W116);
    cudaGetSymbolAddress((void**)&w216, d_W216);

    dim3 tb(32, 8);
    transconv<<<dim3(QKVD / 32, DMODEL / 32, 18), tb>>>(Wq, wq16, DMODEL, QKVD);
    transconv<<<dim3(QKVD / 32, DMODEL / 32, 18), tb>>>(Wk, wk16, DMODEL, QKVD);
    transconv<<<dim3(QKVD / 32, DMODEL / 32, 18), tb>>>(Wv, wv16, DMODEL, QKVD);
    transconv<<<dim3(DMODEL / 32, QKVD / 32, 18), tb>>>(Wo, wo16, QKVD, DMODEL);
    transconv<<<dim3(DMODEL / 32, DMODEL / 32, 18), tb>>>(Wc, wc16, DMODEL, DMODEL);
    transconv<<<dim3(FFD / 32, DMODEL / 32, 6), tb>>>(W1, w116, DMODEL, FFD);
    transconv<<<dim3(DMODEL / 32, FFD / 32, 6), tb>>>(W2, w216, FFD, DMODEL);

    colsum_kernel<<<1, DMODEL>>>(patch_W, csp);
    init_h_kernel<<<NPATCH, DMODEL>>>(csp, ln_in_b, patch_b, pos_emb, hp, h16p);

    layers_kernel<<<NBLK, 256, DSMEM>>>(
        wq16, wk16, wv16, wo16, wc16, w116, w216,
        bq, bk, bv, bo, bc, b1, b2,
        ln1_g, ln1_b, ln2_g, ln2_b,
        hp, h16p, pool16p, qp, kp, vp, o16p, ao16p, ff16p, partp);

    head_kernel<<<1, NCLS>>>(hp, head_W, head_b, out);
}

// round 16
// speedup vs baseline: 1.1817x; 1.1817x over previous
#include <cuda_runtime.h>
#include <cuda_fp16.h>
#include <cstdint>
#include <math.h>

// ---------------- problem constants ----------------
#define NPATCH 500
#define DMODEL 512
#define KDIM   32
#define QKVD   160
#define FFD    2048
#define NLAYER 6
#define NBATCH 32
#define NCLS   256
#define LN_EPS 1e-3f
#define RTOT 875     // rows: scale1 [0,500), scale2 [500,750), scale4 [750,875)

// fp16 GEMM smem (halves): A: [s*2560 + m*40 + k], B: [7680 + s*2560 + n*40 + k]
#define AST 2560
#define BBASE 7680
#define SMEMB 30720   // bytes

// ---------------- scratch ----------------
__device__ float  d_h   [NPATCH * DMODEL];
__device__ __half d_h16 [NPATCH * DMODEL];
__device__ float  d_q   [RTOT * QKVD];
__device__ float  d_k   [RTOT * QKVD];
__device__ float  d_v   [RTOT * QKVD];
__device__ __half d_o16 [RTOT * QKVD];
__device__ __half d_ff16[NPATCH * FFD];
__device__ float  d_part[4 * NPATCH * DMODEL];
__device__ float  d_cs  [DMODEL];
__device__ float  d_bcomb[18 * DMODEL];
// fp16 weights
__device__ __half d_Wq16 [18 * QKVD * DMODEL];   // [z][n=160][k=512]
__device__ __half d_Wk16 [18 * QKVD * DMODEL];
__device__ __half d_Wv16 [18 * QKVD * DMODEL];
__device__ __half d_Wo16n[18 * QKVD * DMODEL];   // non-transposed [z][160][512]
__device__ __half d_Wc16 [18 * DMODEL * DMODEL]; // [z][n=512][k=512]
__device__ __half d_Wow16[18 * DMODEL * QKVD];   // fused (Wo@Wc)^T: [z][n=512][k=160]
__device__ __half d_W116 [6 * FFD * DMODEL];
__device__ __half d_W216 [6 * DMODEL * FFD];

// ---------------- helpers ----------------
__device__ __forceinline__ uint32_t smem_u32(const void* p) {
    return (uint32_t)__cvta_generic_to_shared(p);
}
__device__ __forceinline__ void cp16(uint32_t dst, const void* src) {
    asm volatile("cp.async.cg.shared.global [%0], [%1], 16;\n" :: "r"(dst), "l"(src));
}
__device__ __forceinline__ void cp_commit() { asm volatile("cp.async.commit_group;\n"); }
__device__ __forceinline__ void ldsm4(uint32_t& d0, uint32_t& d1, uint32_t& d2, uint32_t& d3,
                                      uint32_t addr) {
    asm volatile("ldmatrix.sync.aligned.m8n8.x4.shared.b16 {%0,%1,%2,%3}, [%4];"
                 : "=r"(d0), "=r"(d1), "=r"(d2), "=r"(d3) : "r"(addr));
}
__device__ __forceinline__ void mma_f16(float* c, const uint32_t* a, uint32_t b0, uint32_t b1) {
    asm volatile(
        "mma.sync.aligned.m16n8k16.row.col.f32.f16.f16.f32 "
        "{%0,%1,%2,%3}, {%4,%5,%6,%7}, {%8,%9}, {%0,%1,%2,%3};"
        : "+f"(c[0]), "+f"(c[1]), "+f"(c[2]), "+f"(c[3])
        : "r"(a[0]), "r"(a[1]), "r"(a[2]), "r"(a[3]), "r"(b0), "r"(b1));
}
__device__ __forceinline__ float gelu_f(float x) {
    return 0.5f * x * (1.f + erff(x * 0.70710678118654752f));
}

// ---------------- batched transpose/convert preamble ----------------
struct TCSeg { const float* src; __half* dst; int K, N, nx, ny, base, notrans; };
struct TCParams { TCSeg s[7]; };

__global__ void transconv_all(TCParams P) {
    __shared__ float tile[32][33];
    const int fb = blockIdx.x;
    int i = 0;
    #pragma unroll
    for (int s = 1; s < 7; s++) if (fb >= P.s[s].base) i = s;
    const TCSeg sg = P.s[i];
    const int local = fb - sg.base;
    const int per = sg.nx * sg.ny;
    const int b = local / per, rem = local - b * per;
    const int y = rem / sg.nx, x = rem - y * sg.nx;
    const float* src = sg.src + (size_t)b * sg.K * sg.N;
    __half* dst = sg.dst + (size_t)b * sg.K * sg.N;
    const int n0 = x * 32, k0 = y * 32;
    const int tx = threadIdx.x, ty = threadIdx.y;   // 32 x 8
    if (sg.notrans) {
        #pragma unroll
        for (int r = 0; r < 32; r += 8)
            dst[(size_t)(k0 + ty + r) * sg.N + n0 + tx] =
                __float2half_rn(src[(size_t)(k0 + ty + r) * sg.N + n0 + tx]);
    } else {
        #pragma unroll
        for (int r = 0; r < 32; r += 8)
            tile[ty + r][tx] = src[(size_t)(k0 + ty + r) * sg.N + n0 + tx];
        __syncthreads();
        #pragma unroll
        for (int r = 0; r < 32; r += 8)
            dst[(size_t)(n0 + ty + r) * sg.K + k0 + tx] = __float2half_rn(tile[tx][ty + r]);
    }
}

// ---------------- fp16 GEMM core (m16n8k16, ldmatrix, 3-stage cp.async) ----------------
// 256 thr, 8 warps (2m x 4n), warp tile 32x16.
// A fp16 row-major [M][lda] (poolS>1: A rows are averages of poolS consecutive rows);
// Bt fp16 n-major [N][ldb]. kLen % 32 == 0, T >= 2.
__device__ __forceinline__ void gemm_core(
    const __half* __restrict__ A, const __half* __restrict__ Bt,
    const float* __restrict__ bias, float* __restrict__ C, __half* __restrict__ C16,
    int M, int N, int lda, int ldb, int kOff, int kLen,
    int bM, int bN, int act, int addBias, int ldc, int poolS)
{
    extern __shared__ __half smh[];
    const int tid = threadIdx.x, lane = tid & 31, warp = tid >> 5;
    const int wm = (warp & 1) << 5;
    const int wn = (warp >> 1) << 4;
    const int g = lane >> 2, t = lane & 3;
    const int lrow = (lane & 7) + ((lane >> 3) & 1) * 8;
    const int lk8 = (lane >> 4) << 3;

    const int frow = tid >> 2;
    const int fch = (tid & 3) << 3;
    const __half* aSrc = A + (size_t)(min(bM + frow, M - 1) * poolS) * lda + kOff + fch;
    const __half* bSrc = Bt + (size_t)min(bN + frow, N - 1) * ldb + kOff + fch;
    uint32_t aD[3], bD[3];
    int aOffE[3];
    #pragma unroll
    for (int s = 0; s < 3; ++s) {
        aOffE[s] = s * AST + frow * 40 + fch;
        aD[s] = smem_u32(&smh[aOffE[s]]);
        bD[s] = smem_u32(&smh[BBASE + s * AST + frow * 40 + fch]);
    }
    const float pinv = (poolS == 2) ? 0.5f : 0.25f;

    const int T = kLen >> 5;
    #pragma unroll
    for (int p = 0; p < 2; ++p) {
        const int ko = p << 5;
        if (poolS == 1) {
            cp16(aD[p], aSrc + ko);
        } else {
            float acc8[8] = {};
            for (int j = 0; j < poolS; ++j) {
                uint4 u = *(const uint4*)(aSrc + (size_t)j * lda + ko);
                const __half2* h2 = (const __half2*)&u;
                #pragma unroll
                for (int q2 = 0; q2 < 4; ++q2) {
                    float2 f = __half22float2(h2[q2]);
                    acc8[2 * q2] += f.x; acc8[2 * q2 + 1] += f.y;
                }
            }
            uint4 ow;
            __half2* oh = (__half2*)&ow;
            #pragma unroll
            for (int q2 = 0; q2 < 4; ++q2)
                oh[q2] = __floats2half2_rn(acc8[2 * q2] * pinv, acc8[2 * q2 + 1] * pinv);
            *(uint4*)&smh[aOffE[p]] = ow;
        }
        cp16(bD[p], bSrc + ko);
        cp_commit();
    }

    const uint32_t smb = smem_u32(smh);
    uint32_t aFrag[2];
    #pragma unroll
    for (int i = 0; i < 2; ++i)
        aFrag[i] = ((wm + i * 16 + lrow) * 40 + lk8) * 2;
    const uint32_t bFrag = (BBASE + (wn + lrow) * 40 + lk8) * 2;

    float acc[2][2][4] = {};
    int stage = 0;
    for (int tt = 0; tt < T; ++tt) {
        if (tt + 1 < T) { asm volatile("cp.async.wait_group 1;\n"); }
        else            { asm volatile("cp.async.wait_group 0;\n"); }
        __syncthreads();

        if (tt + 2 < T) {
            const int ns = (stage + 2 >= 3) ? stage - 1 : stage + 2;
            const int ko = (tt + 2) << 5;
            if (poolS == 1) {
                cp16(aD[ns], aSrc + ko);
            } else {
                float acc8[8] = {};
                for (int j = 0; j < poolS; ++j) {
                    uint4 u = *(const uint4*)(aSrc + (size_t)j * lda + ko);
                    const __half2* h2 = (const __half2*)&u;
                    #pragma unroll
                    for (int q2 = 0; q2 < 4; ++q2) {
                        float2 f = __half22float2(h2[q2]);
                        acc8[2 * q2] += f.x; acc8[2 * q2 + 1] += f.y;
                    }
                }
                uint4 ow;
                __half2* oh = (__half2*)&ow;
                #pragma unroll
                for (int q2 = 0; q2 < 4; ++q2)
                    oh[q2] = __floats2half2_rn(acc8[2 * q2] * pinv, acc8[2 * q2 + 1] * pinv);
                *(uint4*)&smh[aOffE[ns]] = ow;
            }
            cp16(bD[ns], bSrc + ko);
            cp_commit();
        }

        const uint32_t sb = smb + stage * (AST * 2);
        #pragma unroll
        for (int ks = 0; ks < 2; ++ks) {
            uint32_t af[2][4], bf[4];
            ldsm4(af[0][0], af[0][1], af[0][2], af[0][3], sb + aFrag[0] + ks * 32);
            ldsm4(af[1][0], af[1][1], af[1][2], af[1][3], sb + aFrag[1] + ks * 32);
            ldsm4(bf[0], bf[1], bf[2], bf[3], sb + bFrag + ks * 32);
            mma_f16(acc[0][0], af[0], bf[0], bf[2]);
            mma_f16(acc[0][1], af[0], bf[1], bf[3]);
            mma_f16(acc[1][0], af[1], bf[0], bf[2]);
            mma_f16(acc[1][1], af[1], bf[1], bf[3]);
        }
        stage = (stage + 1 >= 3) ? 0 : stage + 1;
    }

    #pragma unroll
    for (int i = 0; i < 2; ++i) {
        const int r0 = bM + wm + (i << 4) + g;
        const int r1 = r0 + 8;
        #pragma unroll
        for (int j = 0; j < 2; ++j) {
            const int col = bN + wn + (j << 3) + (t << 1);
            if (col >= N) continue;
            float b0v = 0.f, b1v = 0.f;
            if (addBias) {
                float2 bb = *(const float2*)(bias + col);
                b0v = bb.x; b1v = bb.y;
            }
            float c0 = acc[i][j][0] + b0v, c1 = acc[i][j][1] + b1v;
            float c2 = acc[i][j][2] + b0v, c3 = acc[i][j][3] + b1v;
            if (act) { c0 = gelu_f(c0); c1 = gelu_f(c1); c2 = gelu_f(c2); c3 = gelu_f(c3); }
            if (C16) {
                if (r0 < M) {
                    C16[(size_t)r0 * ldc + col] = __float2half_rn(c0);
                    C16[(size_t)r0 * ldc + col + 1] = __float2half_rn(c1);
                }
                if (r1 < M) {
                    C16[(size_t)r1 * ldc + col] = __float2half_rn(c2);
                    C16[(size_t)r1 * ldc + col + 1] = __float2half_rn(c3);
                }
            } else {
                if (r0 < M) *(float2*)(C + (size_t)r0 * ldc + col) = make_float2(c0, c1);
                if (r1 < M) *(float2*)(C + (size_t)r1 * ldc + col) = make_float2(c2, c3);
            }
        }
    }
}

// ---------------- GEMM wrappers ----------------
__constant__ int c_Ms[3] = {500, 250, 125};
__constant__ int c_ro[3] = {0, 500, 750};
__constant__ int c_sc[3] = {1, 2, 4};

// Wow = Wc^T @ Wo (per z): A=wc16[z] (512x512), Bt=Wo16n[z] (160x512) -> fp16 [512][160]
__global__ void __launch_bounds__(256) gemm_wow(
    const __half* __restrict__ wc16, const __half* __restrict__ wo16n,
    __half* __restrict__ wow16)
{
    int z = blockIdx.z;
    gemm_core(wc16 + (size_t)z * DMODEL * DMODEL, wo16n + (size_t)z * QKVD * DMODEL,
              nullptr, nullptr, wow16 + (size_t)z * DMODEL * QKVD,
              DMODEL, QKVD, DMODEL, DMODEL, 0, DMODEL,
              blockIdx.y * 64, blockIdx.x * 64, 0, 0, QKVD, 1);
}

// bcomb[z][d] = sum_k bo[z][k] * Wc[l][si*512+k][d]
__global__ void bcomb_kernel(const float* __restrict__ Wc, const float* __restrict__ bo,
                             float* __restrict__ bcomb)
{
    int z = blockIdx.x;
    int d = threadIdx.x;   // 512
    __shared__ float bos[DMODEL];
    bos[d] = bo[(size_t)z * DMODEL + d];
    __syncthreads();
    const float* wcp = Wc + (size_t)z * DMODEL * DMODEL + d;
    float acc = 0.f;
    #pragma unroll 4
    for (int k2 = 0; k2 < DMODEL; k2++)
        acc += bos[k2] * wcp[(size_t)k2 * DMODEL];
    bcomb[(size_t)z * DMODEL + d] = acc;
}

// qkv with fused pooling: z = si*3 + which; writes fp32 q/k/v with bias
__global__ void __launch_bounds__(256) gemm_qkv(
    const __half* __restrict__ h16,
    const __half* __restrict__ Wq, const __half* __restrict__ Wk,
    const __half* __restrict__ Wv,
    const float* __restrict__ bq, const float* __restrict__ bk,
    const float* __restrict__ bv,
    float* __restrict__ q, float* __restrict__ k, float* __restrict__ v)
{
    int z = blockIdx.z;
    int si = z / 3, which = z - si * 3;
    int M = c_Ms[si];
    int bM = blockIdx.y * 64;
    if (bM >= M) return;
    const __half* W = (which == 0) ? Wq : (which == 1) ? Wk : Wv;
    const float* bb = (which == 0) ? bq : (which == 1) ? bk : bv;
    float* Cb = (which == 0) ? q : (which == 1) ? k : v;
    gemm_core(h16, W + (size_t)si * QKVD * DMODEL, bb + (size_t)si * QKVD,
              Cb + (size_t)c_ro[si] * QKVD, nullptr,
              M, QKVD, DMODEL, DMODEL, 0, DMODEL, bM, blockIdx.x * 64, 0, 1, QKVD,
              c_sc[si]);
}

// comb on pooled rows via fused weight: K=160, z = si, partial P[si]
__global__ void __launch_bounds__(256) gemm_comb(
    const __half* __restrict__ o16, const __half* __restrict__ wowl,
    float* __restrict__ P)
{
    int si = blockIdx.z;
    int M = c_Ms[si];
    int bM = blockIdx.y * 64;
    if (bM >= M) return;
    gemm_core(o16 + (size_t)c_ro[si] * QKVD, wowl + (size_t)si * DMODEL * QKVD,
              nullptr, P + (size_t)si * NPATCH * DMODEL, nullptr,
              M, DMODEL, QKVD, QKVD, 0, QKVD, bM, blockIdx.x * 64, 0, 0, DMODEL, 1);
}

// ffn1: h16 @ W1t + b1 -> gelu -> ff16
__global__ void __launch_bounds__(256) gemm_ffn1(
    const __half* __restrict__ h16, const __half* __restrict__ W1t,
    const float* __restrict__ b1, __half* __restrict__ ff16)
{
    int bM = blockIdx.y * 64;
    if (bM >= NPATCH) return;
    gemm_core(h16, W1t, b1, nullptr, ff16, NPATCH, FFD, DMODEL, DMODEL, 0, DMODEL,
              bM, blockIdx.x * 64, 1, 1, FFD, 1);
}

// ffn2 split-K 4: z chunks of 512 over K=2048
__global__ void __launch_bounds__(256) gemm_ffn2(
    const __half* __restrict__ ff16, const __half* __restrict__ W2t,
    float* __restrict__ part)
{
    int bM = blockIdx.y * 64;
    if (bM >= NPATCH) return;
    int z = blockIdx.z;
    gemm_core(ff16, W2t, nullptr, part + (size_t)z * NPATCH * DMODEL, nullptr,
              NPATCH, DMODEL, FFD, FFD, z * 512, 512, bM, blockIdx.x * 64, 0, 0, DMODEL, 1);
}

// ---------------- small kernels ----------------
__global__ void colsum_kernel(const float* __restrict__ W, float* __restrict__ cs) {
    int d = threadIdx.x;
    float s = 0.f;
    #pragma unroll 4
    for (int p = 0; p < 100; p++) s += W[p * DMODEL + d];
    cs[d] = s;
}

__global__ void init_h_kernel(const float* __restrict__ cs, const float* __restrict__ ln_in_b,
                              const float* __restrict__ patch_b, const float* __restrict__ pos,
                              float* __restrict__ h, __half* __restrict__ h16) {
    int n = blockIdx.x, d = threadIdx.x;
    float v = ln_in_b[0] * cs[d] + patch_b[d] + pos[n * DMODEL + d];
    h[n * DMODEL + d] = v;
    h16[n * DMODEL + d] = __float2half_rn(v);
}

// ---------------- attention (fp32 in, fp16 out) ----------------
__global__ void __launch_bounds__(256) attn_kernel(
    const float* __restrict__ q, const float* __restrict__ k,
    const float* __restrict__ v, __half* __restrict__ o16)
{
    __shared__ float Ks[32][34];
    __shared__ float Vs[32][34];
    __shared__ float OS[8][32][34];

    const int b = blockIdx.x;
    int Ns, ro, h, qg;
    if (b < 315)      { Ns = 500; ro = 0;   h = b / 63;  qg = b % 63; }
    else if (b < 475) { int c = b - 315; Ns = 250; ro = 500; h = c / 32; qg = c % 32; }
    else              { int c = b - 475; Ns = 125; ro = 750; h = c / 16; qg = c % 16; }

    const int wid = threadIdx.x >> 5;
    const int lane = threadIdx.x & 31;
    const int n = qg * 8 + wid;
    const bool valid = n < Ns;
    const int nq = valid ? n : (Ns - 1);
    const float scale = 0.1767766952966369f;

    float2 qr[16];
    {
        const float2* qp = (const float2*)(q + (size_t)(ro + nq) * QKVD + h * KDIM);
        #pragma unroll
        for (int i = 0; i < 16; i++) {
            float2 tq = qp[i];
            qr[i] = make_float2(tq.x * scale, tq.y * scale);
        }
    }

    float mmax = -INFINITY, ssum = 0.f;
    float oa[32];
    #pragma unroll
    for (int d = 0; d < 32; d++) oa[d] = 0.f;

    const int nt = (Ns + 31) >> 5;
    for (int tt = 0; tt < nt; tt++) {
        const int kt = tt << 5;
        {
            const int m = threadIdx.x >> 3;
            const int dq = (threadIdx.x & 7) << 2;
            const int row = min(kt + m, Ns - 1);
            const float4 kk = *(const float4*)(k + (size_t)(ro + row) * QKVD + h * KDIM + dq);
            const float4 vv = *(const float4*)(v + (size_t)(ro + row) * QKVD + h * KDIM + dq);
            *(float2*)&Ks[m][dq]     = make_float2(kk.x, kk.y);
            *(float2*)&Ks[m][dq + 2] = make_float2(kk.z, kk.w);
            *(float2*)&Vs[m][dq]     = make_float2(vv.x, vv.y);
            *(float2*)&Vs[m][dq + 2] = make_float2(vv.z, vv.w);
        }
        __syncthreads();

        float s0 = 0.f, s1 = 0.f;
        #pragma unroll
        for (int i = 0; i < 16; i++) {
            float2 kk = *(const float2*)&Ks[lane][2 * i];
            s0 = fmaf(qr[i].x, kk.x, s0);
            s1 = fmaf(qr[i].y, kk.y, s1);
        }
        float s = s0 + s1;
        if (kt + lane >= Ns) s = -INFINITY;

        float nm = fmaxf(mmax, s);
        float corr = __expf(mmax - nm);
        float p = __expf(s - nm);
        ssum = ssum * corr + p;
        #pragma unroll
        for (int i = 0; i < 16; i++) {
            float2 vv = *(const float2*)&Vs[lane][2 * i];
            oa[2 * i]     = oa[2 * i]     * corr + p * vv.x;
            oa[2 * i + 1] = oa[2 * i + 1] * corr + p * vv.y;
        }
        mmax = nm;
        __syncthreads();
    }

    float gm = mmax;
    #pragma unroll
    for (int off = 16; off; off >>= 1) gm = fmaxf(gm, __shfl_xor_sync(0xffffffffu, gm, off));
    float c = __expf(mmax - gm);
    float ss = ssum * c;
    #pragma unroll
    for (int off = 16; off; off >>= 1) ss += __shfl_xor_sync(0xffffffffu, ss, off);

    #pragma unroll
    for (int i = 0; i < 16; i++)
        *(float2*)&OS[wid][lane][2 * i] = make_float2(oa[2 * i] * c, oa[2 * i + 1] * c);
    __syncwarp();

    float accd = 0.f;
    #pragma unroll
    for (int m = 0; m < 32; m++) accd += OS[wid][m][lane];
    if (valid)
        o16[(size_t)(ro + n) * QKVD + h * KDIM + lane] = __float2half_rn(accd / ss);
}

// LN finish: write fp32 h and fp16 h16
__device__ __forceinline__ void ln_finish(float v0, float v1, int n, int t,
                                          float* red, float* statp,
                                          float* __restrict__ h, __half* __restrict__ h16,
                                          const float* __restrict__ g,
                                          const float* __restrict__ b) {
    float s = v0 + v1;
    #pragma unroll
    for (int o = 16; o; o >>= 1) s += __shfl_xor_sync(0xffffffffu, s, o);
    if ((t & 31) == 0) red[t >> 5] = s;
    __syncthreads();
    if (t < 32) {
        float x = (t < 8) ? red[t] : 0.f;
        #pragma unroll
        for (int o = 4; o; o >>= 1) x += __shfl_xor_sync(0xffffffffu, x, o);
        if (t == 0) *statp = x / (float)DMODEL;
    }
    __syncthreads();
    float mean = *statp;
    float dd0 = v0 - mean, dd1 = v1 - mean;
    __syncthreads();
    float vs = dd0 * dd0 + dd1 * dd1;
    #pragma unroll
    for (int o = 16; o; o >>= 1) vs += __shfl_xor_sync(0xffffffffu, vs, o);
    if ((t & 31) == 0) red[t >> 5] = vs;
    __syncthreads();
    if (t < 32) {
        float x = (t < 8) ? red[t] : 0.f;
        #pragma unroll
        for (int o = 4; o; o >>= 1) x += __shfl_xor_sync(0xffffffffu, x, o);
        if (t == 0) *statp = rsqrtf(x / (float)DMODEL + LN_EPS);
    }
    __syncthreads();
    float rstd = *statp;
    float o0 = dd0 * rstd * g[t] + b[t];
    float o1 = dd1 * rstd * g[t + 256] + b[t + 256];
    h[n * DMODEL + t] = o0;
    h[n * DMODEL + t + 256] = o1;
    h16[n * DMODEL + t] = __float2half_rn(o0);
    h16[n * DMODEL + t + 256] = __float2half_rn(o1);
}

// comb partials (3 scales, upsampled) + bcomb biases + residual + LN
__global__ void reduce_comb_ln(const float* __restrict__ P,
                               const float* __restrict__ bias,
                               const float* __restrict__ bcl,   // bcomb + l*3*512
                               float* __restrict__ h, __half* __restrict__ h16,
                               const float* __restrict__ g,
                               const float* __restrict__ b) {
    int n = blockIdx.x, t = threadIdx.x;
    __shared__ float red[8];
    __shared__ float stat;
    const size_t ND = (size_t)NPATCH * DMODEL;
    const int n2 = n >> 1, n4 = n >> 2;
    float bsum0 = bias[t] + bcl[t] + bcl[DMODEL + t] + bcl[2 * DMODEL + t];
    float bsum1 = bias[t + 256] + bcl[t + 256] + bcl[DMODEL + t + 256]
                + bcl[2 * DMODEL + t + 256];
    float v0 = h[n * DMODEL + t]       + bsum0;
    float v1 = h[n * DMODEL + t + 256] + bsum1;
    v0 += P[0 * ND + (size_t)n  * DMODEL + t];
    v1 += P[0 * ND + (size_t)n  * DMODEL + t + 256];
    v0 += P[1 * ND + (size_t)n2 * DMODEL + t];
    v1 += P[1 * ND + (size_t)n2 * DMODEL + t + 256];
    v0 += P[2 * ND + (size_t)n4 * DMODEL + t];
    v1 += P[2 * ND + (size_t)n4 * DMODEL + t + 256];
    ln_finish(v0, v1, n, t, red, &stat, h, h16, g, b);
}

// ffn2 partials + residual + LN
__global__ void reduce_add_ln(const float* __restrict__ part, int S,
                              const float* __restrict__ bias,
                              float* __restrict__ h, __half* __restrict__ h16,
                              const float* __restrict__ g,
                              const float* __restrict__ b) {
    int n = blockIdx.x, t = threadIdx.x;
    __shared__ float red[8];
    __shared__ float stat;
    float v0 = h[n * DMODEL + t]       + bias[t];
    float v1 = h[n * DMODEL + t + 256] + bias[t + 256];
    for (int s = 0; s < S; s++) {
        v0 += part[(size_t)s * NPATCH * DMODEL + n * DMODEL + t];
        v1 += part[(size_t)s * NPATCH * DMODEL + n * DMODEL + t + 256];
    }
    ln_finish(v0, v1, n, t, red, &stat, h, h16, g, b);
}

// fused global-mean-pool + head + softmax + broadcast
__global__ void head_kernel(const float* __restrict__ h, const float* __restrict__ W,
                            const float* __restrict__ b, float* __restrict__ out) {
    __shared__ float gs[DMODEL];
    __shared__ float red[8];
    __shared__ float stat;
    int t = threadIdx.x;
    {
        float s0 = 0.f, s1 = 0.f;
        for (int n = 0; n < NPATCH; n++) {
            s0 += h[n * DMODEL + t];
            s1 += h[n * DMODEL + t + 256];
        }
        gs[t] = s0 / (float)NPATCH;
        gs[t + 256] = s1 / (float)NPATCH;
    }
    __syncthreads();
    float acc = b[t];
    #pragma unroll 4
    for (int d = 0; d < DMODEL; d++) acc += gs[d] * W[d * NCLS + t];

    float m = acc;
    #pragma unroll
    for (int o = 16; o; o >>= 1) m = fmaxf(m, __shfl_xor_sync(0xffffffffu, m, o));
    if ((t & 31) == 0) red[t >> 5] = m;
    __syncthreads();
    if (t < 32) {
        float x = (t < 8) ? red[t] : -INFINITY;
        #pragma unroll
        for (int o = 4; o; o >>= 1) x = fmaxf(x, __shfl_xor_sync(0xffffffffu, x, o));
        if (t == 0) stat = x;
    }
    __syncthreads();
    float e = expf(acc - stat);
    __syncthreads();
    float s = e;
    #pragma unroll
    for (int o = 16; o; o >>= 1) s += __shfl_xor_sync(0xffffffffu, s, o);
    if ((t & 31) == 0) red[t >> 5] = s;
    __syncthreads();
    if (t < 32) {
        float x = (t < 8) ? red[t] : 0.f;
        #pragma unroll
        for (int o = 4; o; o >>= 1) x += __shfl_xor_sync(0xffffffffu, x, o);
        if (t == 0) stat = x;
    }
    __syncthreads();
    float p = e / stat;
    for (int bb = 0; bb < NBATCH; bb++) out[bb * NCLS + t] = p;
}

// ---------------- host launcher ----------------
extern "C" void kernel_launch(void* const* d_in, const int* in_sizes, int n_in,
                              void* d_out, int out_size) {
    const float* ln_in_b = (const float*)d_in[2];
    const float* patch_W = (const float*)d_in[3];
    const float* patch_b = (const float*)d_in[4];
    const float* pos_emb = (const float*)d_in[5];
    const float* Wq = (const float*)d_in[6];
    const float* bq = (const float*)d_in[7];
    const float* Wk = (const float*)d_in[8];
    const float* bk = (const float*)d_in[9];
    const float* Wv = (const float*)d_in[10];
    const float* bv = (const float*)d_in[11];
    const float* Wo = (const float*)d_in[12];
    const float* bo = (const float*)d_in[13];
    const float* Wc = (const float*)d_in[14];
    const float* bc = (const float*)d_in[15];
    const float* ln1_g = (const float*)d_in[16];
    const float* ln1_b = (const float*)d_in[17];
    const float* W1 = (const float*)d_in[18];
    const float* b1 = (const float*)d_in[19];
    const float* W2 = (const float*)d_in[20];
    const float* b2 = (const float*)d_in[21];
    const float* ln2_g = (const float*)d_in[22];
    const float* ln2_b = (const float*)d_in[23];
    const float* head_W = (const float*)d_in[24];
    const float* head_b = (const float*)d_in[25];
    float* out = (float*)d_out;

    float *hp, *qp, *kp, *vp, *partp, *csp, *bcombp;
    __half *h16p, *o16p, *ff16p;
    __half *wq16, *wk16, *wv16, *wo16n, *wc16, *wow16, *w116, *w216;
    cudaGetSymbolAddress((void**)&hp,  d_h);
    cudaGetSymbolAddress((void**)&h16p, d_h16);
    cudaGetSymbolAddress((void**)&qp,  d_q);
    cudaGetSymbolAddress((void**)&kp,  d_k);
    cudaGetSymbolAddress((void**)&vp,  d_v);
    cudaGetSymbolAddress((void**)&o16p, d_o16);
    cudaGetSymbolAddress((void**)&ff16p, d_ff16);
    cudaGetSymbolAddress((void**)&partp, d_part);
    cudaGetSymbolAddress((void**)&csp, d_cs);
    cudaGetSymbolAddress((void**)&bcombp, d_bcomb);
    cudaGetSymbolAddress((void**)&wq16, d_Wq16);
    cudaGetSymbolAddress((void**)&wk16, d_Wk16);
    cudaGetSymbolAddress((void**)&wv16, d_Wv16);
    cudaGetSymbolAddress((void**)&wo16n, d_Wo16n);
    cudaGetSymbolAddress((void**)&wc16, d_Wc16);
    cudaGetSymbolAddress((void**)&wow16, d_Wow16);
    cudaGetSymbolAddress((void**)&w116, d_W116);
    cudaGetSymbolAddress((void**)&w216, d_W216);

    // batched transpose/convert: 7 segments in one launch
    TCParams P;
    int base = 0;
    auto seg = [&](int i, const float* s, __half* d, int K, int N, int nb, int notrans) {
        P.s[i].src = s; P.s[i].dst = d; P.s[i].K = K; P.s[i].N = N;
        P.s[i].nx = N / 32; P.s[i].ny = K / 32; P.s[i].base = base; P.s[i].notrans = notrans;
        base += (N / 32) * (K / 32) * nb;
    };
    seg(0, Wq, wq16, DMODEL, QKVD, 18, 0);
    seg(1, Wk, wk16, DMODEL, QKVD, 18, 0);
    seg(2, Wv, wv16, DMODEL, QKVD, 18, 0);
    seg(3, Wc, wc16, DMODEL, DMODEL, 18, 0);
    seg(4, W1, w116, DMODEL, FFD, 6, 0);
    seg(5, W2, w216, FFD, DMODEL, 6, 0);
    seg(6, Wo, wo16n, QKVD, DMODEL, 18, 1);

    dim3 tb(32, 8);
    transconv_all<<<base, tb>>>(P);
    gemm_wow<<<dim3(3, 8, 18), 256, SMEMB>>>(wc16, wo16n, wow16);
    bcomb_kernel<<<18, DMODEL>>>(Wc, bo, bcombp);
    colsum_kernel<<<1, DMODEL>>>(patch_W, csp);
    init_h_kernel<<<NPATCH, DMODEL>>>(csp, ln_in_b, patch_b, pos_emb, hp, h16p);

    for (int l = 0; l < NLAYER; l++) {
        size_t bqkv = (size_t)l * 3 * QKVD;

        gemm_qkv<<<dim3(3, 8, 9), 256, SMEMB>>>(h16p,
            wq16 + (size_t)l * 3 * QKVD * DMODEL,
            wk16 + (size_t)l * 3 * QKVD * DMODEL,
            wv16 + (size_t)l * 3 * QKVD * DMODEL,
            bq + bqkv, bk + bqkv, bv + bqkv, qp, kp, vp);
        attn_kernel<<<555, 256>>>(qp, kp, vp, o16p);

        gemm_comb<<<dim3(8, 8, 3), 256, SMEMB>>>(o16p,
            wow16 + (size_t)l * 3 * DMODEL * QKVD, partp);
        reduce_comb_ln<<<NPATCH, 256>>>(partp, bc + (size_t)l * DMODEL,
                                        bcombp + (size_t)l * 3 * DMODEL, hp, h16p,
                                        ln1_g + l * DMODEL, ln1_b + l * DMODEL);

        gemm_ffn1<<<dim3(32, 8), 256, SMEMB>>>(h16p,
            w116 + (size_t)l * FFD * DMODEL, b1 + (size_t)l * FFD, ff16p);
        gemm_ffn2<<<dim3(8, 8, 4), 256, SMEMB>>>(ff16p,
            w216 + (size_t)l * DMODEL * FFD, partp);
        reduce_add_ln<<<NPATCH, 256>>>(partp, 4, b2 + (size_t)l * DMODEL, hp, h16p,
                                       ln2_g + l * DMODEL, ln2_b + l * DMODEL);
    }

    head_kernel<<<1, NCLS>>>(hp, head_W, head_b, out);
}

// round 17
// speedup vs baseline: 1.4758x; 1.2488x over previous
#include <cuda_runtime.h>
#include <cuda_fp16.h>
#include <cstdint>
#include <math.h>

// ---------------- problem constants ----------------
#define NPATCH 500
#define DMODEL 512
#define KDIM   32
#define QKVD   160
#define FFD    2048
#define NLAYER 6
#define NBATCH 32
#define NCLS   256
#define LN_EPS 1e-3f
#define RTOT 875     // rows: scale1 [0,500), scale2 [500,750), scale4 [750,875)

// fp16 GEMM smem (halves): A: [s*2560 + m*40 + k], B: [7680 + s*2560 + n*40 + k]
#define AST 2560
#define BBASE 7680
#define SMEMB 30720   // bytes

// ---------------- scratch ----------------
__device__ float  d_h   [NPATCH * DMODEL];
__device__ __half d_h16 [NPATCH * DMODEL];
__device__ __half d_pool16[375 * DMODEL];
__device__ float  d_q   [RTOT * QKVD];
__device__ float  d_k   [RTOT * QKVD];
__device__ float  d_v   [RTOT * QKVD];
__device__ __half d_o16 [RTOT * QKVD];
__device__ __half d_ff16[NPATCH * FFD];
__device__ float  d_part[4 * NPATCH * DMODEL];
__device__ float  d_cs  [DMODEL];
__device__ float  d_bcomb[18 * DMODEL];
// fp16 weights
__device__ __half d_Wq16 [18 * QKVD * DMODEL];   // [z][n=160][k=512]
__device__ __half d_Wk16 [18 * QKVD * DMODEL];
__device__ __half d_Wv16 [18 * QKVD * DMODEL];
__device__ __half d_Wo16n[18 * QKVD * DMODEL];   // non-transposed [z][160][512]
__device__ __half d_Wc16 [18 * DMODEL * DMODEL]; // [z][n=512][k=512]
__device__ __half d_Wow16[18 * DMODEL * QKVD];   // fused (Wo@Wc)^T: [z][n=512][k=160]
__device__ __half d_W116 [6 * FFD * DMODEL];
__device__ __half d_W216 [6 * DMODEL * FFD];

// ---------------- helpers ----------------
__device__ __forceinline__ uint32_t smem_u32(const void* p) {
    return (uint32_t)__cvta_generic_to_shared(p);
}
__device__ __forceinline__ void cp16(uint32_t dst, const void* src) {
    asm volatile("cp.async.cg.shared.global [%0], [%1], 16;\n" :: "r"(dst), "l"(src));
}
__device__ __forceinline__ void cp_commit() { asm volatile("cp.async.commit_group;\n"); }
__device__ __forceinline__ void ldsm4(uint32_t& d0, uint32_t& d1, uint32_t& d2, uint32_t& d3,
                                      uint32_t addr) {
    asm volatile("ldmatrix.sync.aligned.m8n8.x4.shared.b16 {%0,%1,%2,%3}, [%4];"
                 : "=r"(d0), "=r"(d1), "=r"(d2), "=r"(d3) : "r"(addr));
}
__device__ __forceinline__ void mma_f16(float* c, const uint32_t* a, uint32_t b0, uint32_t b1) {
    asm volatile(
        "mma.sync.aligned.m16n8k16.row.col.f32.f16.f16.f32 "
        "{%0,%1,%2,%3}, {%4,%5,%6,%7}, {%8,%9}, {%0,%1,%2,%3};"
        : "+f"(c[0]), "+f"(c[1]), "+f"(c[2]), "+f"(c[3])
        : "r"(a[0]), "r"(a[1]), "r"(a[2]), "r"(a[3]), "r"(b0), "r"(b1));
}
__device__ __forceinline__ float gelu_f(float x) {
    return 0.5f * x * (1.f + erff(x * 0.70710678118654752f));
}

// ---------------- batched transpose/convert preamble ----------------
struct TCSeg { const float* src; __half* dst; int K, N, nx, ny, base, notrans; };
struct TCParams { TCSeg s[7]; };

__global__ void transconv_all(TCParams P) {
    __shared__ float tile[32][33];
    const int fb = blockIdx.x;
    int i = 0;
    #pragma unroll
    for (int s = 1; s < 7; s++) if (fb >= P.s[s].base) i = s;
    const TCSeg sg = P.s[i];
    const int local = fb - sg.base;
    const int per = sg.nx * sg.ny;
    const int b = local / per, rem = local - b * per;
    const int y = rem / sg.nx, x = rem - y * sg.nx;
    const float* src = sg.src + (size_t)b * sg.K * sg.N;
    __half* dst = sg.dst + (size_t)b * sg.K * sg.N;
    const int n0 = x * 32, k0 = y * 32;
    const int tx = threadIdx.x, ty = threadIdx.y;   // 32 x 8
    if (sg.notrans) {
        #pragma unroll
        for (int r = 0; r < 32; r += 8)
            dst[(size_t)(k0 + ty + r) * sg.N + n0 + tx] =
                __float2half_rn(src[(size_t)(k0 + ty + r) * sg.N + n0 + tx]);
    } else {
        #pragma unroll
        for (int r = 0; r < 32; r += 8)
            tile[ty + r][tx] = src[(size_t)(k0 + ty + r) * sg.N + n0 + tx];
        __syncthreads();
        #pragma unroll
        for (int r = 0; r < 32; r += 8)
            dst[(size_t)(n0 + ty + r) * sg.K + k0 + tx] = __float2half_rn(tile[tx][ty + r]);
    }
}

// ---------------- fp16 GEMM core (m16n8k16, ldmatrix, 3-stage cp.async) ----------------
// 256 thr, 8 warps (2m x 4n), warp tile 32x16.
// A fp16 row-major [M][lda]; Bt fp16 n-major [N][ldb]. kLen % 32 == 0, T >= 2.
__device__ __forceinline__ void gemm_core(
    const __half* __restrict__ A, const __half* __restrict__ Bt,
    const float* __restrict__ bias, float* __restrict__ C, __half* __restrict__ C16,
    int M, int N, int lda, int ldb, int kOff, int kLen,
    int bM, int bN, int act, int addBias, int ldc)
{
    extern __shared__ __half smh[];
    const int tid = threadIdx.x, lane = tid & 31, warp = tid >> 5;
    const int wm = (warp & 1) << 5;
    const int wn = (warp >> 1) << 4;
    const int g = lane >> 2, t = lane & 3;
    const int lrow = (lane & 7) + ((lane >> 3) & 1) * 8;
    const int lk8 = (lane >> 4) << 3;

    const int frow = tid >> 2;
    const int fch = (tid & 3) << 3;
    const __half* aSrc = A + (size_t)min(bM + frow, M - 1) * lda + kOff + fch;
    const __half* bSrc = Bt + (size_t)min(bN + frow, N - 1) * ldb + kOff + fch;
    uint32_t aD[3], bD[3];
    #pragma unroll
    for (int s = 0; s < 3; ++s) {
        aD[s] = smem_u32(&smh[s * AST + frow * 40 + fch]);
        bD[s] = smem_u32(&smh[BBASE + s * AST + frow * 40 + fch]);
    }

    const int T = kLen >> 5;
    #pragma unroll
    for (int p = 0; p < 2; ++p) {
        cp16(aD[p], aSrc + (p << 5));
        cp16(bD[p], bSrc + (p << 5));
        cp_commit();
    }

    const uint32_t smb = smem_u32(smh);
    uint32_t aFrag[2];
    #pragma unroll
    for (int i = 0; i < 2; ++i)
        aFrag[i] = ((wm + i * 16 + lrow) * 40 + lk8) * 2;
    const uint32_t bFrag = (BBASE + (wn + lrow) * 40 + lk8) * 2;

    float acc[2][2][4] = {};
    int stage = 0;
    for (int tt = 0; tt < T; ++tt) {
        if (tt + 1 < T) { asm volatile("cp.async.wait_group 1;\n"); }
        else            { asm volatile("cp.async.wait_group 0;\n"); }
        __syncthreads();

        if (tt + 2 < T) {
            const int ns = (stage + 2 >= 3) ? stage - 1 : stage + 2;
            const int ko = (tt + 2) << 5;
            cp16(aD[ns], aSrc + ko);
            cp16(bD[ns], bSrc + ko);
            cp_commit();
        }

        const uint32_t sb = smb + stage * (AST * 2);
        #pragma unroll
        for (int ks = 0; ks < 2; ++ks) {
            uint32_t af[2][4], bf[4];
            ldsm4(af[0][0], af[0][1], af[0][2], af[0][3], sb + aFrag[0] + ks * 32);
            ldsm4(af[1][0], af[1][1], af[1][2], af[1][3], sb + aFrag[1] + ks * 32);
            ldsm4(bf[0], bf[1], bf[2], bf[3], sb + bFrag + ks * 32);
            mma_f16(acc[0][0], af[0], bf[0], bf[2]);
            mma_f16(acc[0][1], af[0], bf[1], bf[3]);
            mma_f16(acc[1][0], af[1], bf[0], bf[2]);
            mma_f16(acc[1][1], af[1], bf[1], bf[3]);
        }
        stage = (stage + 1 >= 3) ? 0 : stage + 1;
    }

    #pragma unroll
    for (int i = 0; i < 2; ++i) {
        const int r0 = bM + wm + (i << 4) + g;
        const int r1 = r0 + 8;
        #pragma unroll
        for (int j = 0; j < 2; ++j) {
            const int col = bN + wn + (j << 3) + (t << 1);
            if (col >= N) continue;
            float b0v = 0.f, b1v = 0.f;
            if (addBias) {
                float2 bb = *(const float2*)(bias + col);
                b0v = bb.x; b1v = bb.y;
            }
            float c0 = acc[i][j][0] + b0v, c1 = acc[i][j][1] + b1v;
            float c2 = acc[i][j][2] + b0v, c3 = acc[i][j][3] + b1v;
            if (act) { c0 = gelu_f(c0); c1 = gelu_f(c1); c2 = gelu_f(c2); c3 = gelu_f(c3); }
            if (C16) {
                if (r0 < M) {
                    C16[(size_t)r0 * ldc + col] = __float2half_rn(c0);
                    C16[(size_t)r0 * ldc + col + 1] = __float2half_rn(c1);
                }
                if (r1 < M) {
                    C16[(size_t)r1 * ldc + col] = __float2half_rn(c2);
                    C16[(size_t)r1 * ldc + col + 1] = __float2half_rn(c3);
                }
            } else {
                if (r0 < M) *(float2*)(C + (size_t)r0 * ldc + col) = make_float2(c0, c1);
                if (r1 < M) *(float2*)(C + (size_t)r1 * ldc + col) = make_float2(c2, c3);
            }
        }
    }
}

// ---------------- GEMM wrappers ----------------
__constant__ int c_Ms[3] = {500, 250, 125};
__constant__ int c_ro[3] = {0, 500, 750};

// Wow = Wc^T @ Wo (per z): A=wc16[z] (512x512), Bt=Wo16n[z] (160x512) -> fp16 [512][160]
__global__ void __launch_bounds__(256) gemm_wow(
    const __half* __restrict__ wc16, const __half* __restrict__ wo16n,
    __half* __restrict__ wow16)
{
    int z = blockIdx.z;
    gemm_core(wc16 + (size_t)z * DMODEL * DMODEL, wo16n + (size_t)z * QKVD * DMODEL,
              nullptr, nullptr, wow16 + (size_t)z * DMODEL * QKVD,
              DMODEL, QKVD, DMODEL, DMODEL, 0, DMODEL,
              blockIdx.y * 64, blockIdx.x * 64, 0, 0, QKVD);
}

// bcomb[z][d] = sum_k bo[z][k] * Wc[z][k][d]
__global__ void bcomb_kernel(const float* __restrict__ Wc, const float* __restrict__ bo,
                             float* __restrict__ bcomb)
{
    int z = blockIdx.x;
    int d = threadIdx.x;   // 512
    __shared__ float bos[DMODEL];
    bos[d] = bo[(size_t)z * DMODEL + d];
    __syncthreads();
    const float* wcp = Wc + (size_t)z * DMODEL * DMODEL + d;
    float acc = 0.f;
    #pragma unroll 8
    for (int k2 = 0; k2 < DMODEL; k2++)
        acc += bos[k2] * wcp[(size_t)k2 * DMODEL];
    bcomb[(size_t)z * DMODEL + d] = acc;
}

// qkv: z = si*3 + which, writes fp32 q/k/v with fused bias
__global__ void __launch_bounds__(256) gemm_qkv(
    const __half* __restrict__ h16, const __half* __restrict__ pool16,
    const __half* __restrict__ Wq, const __half* __restrict__ Wk,
    const __half* __restrict__ Wv,
    const float* __restrict__ bq, const float* __restrict__ bk,
    const float* __restrict__ bv,
    float* __restrict__ q, float* __restrict__ k, float* __restrict__ v)
{
    int z = blockIdx.z;
    int si = z / 3, which = z - si * 3;
    int M = c_Ms[si];
    int bM = blockIdx.y * 64;
    if (bM >= M) return;
    const __half* A = (si == 0) ? h16 : (pool16 + (si == 2 ? 250 * DMODEL : 0));
    const __half* W = (which == 0) ? Wq : (which == 1) ? Wk : Wv;
    const float* bb = (which == 0) ? bq : (which == 1) ? bk : bv;
    float* Cb = (which == 0) ? q : (which == 1) ? k : v;
    gemm_core(A, W + (size_t)si * QKVD * DMODEL, bb + (size_t)si * QKVD,
              Cb + (size_t)c_ro[si] * QKVD, nullptr,
              M, QKVD, DMODEL, DMODEL, 0, DMODEL, bM, blockIdx.x * 64, 0, 1, QKVD);
}

// comb on pooled rows via fused weight Wow: K=160, z = si, partial P[si]
__global__ void __launch_bounds__(256) gemm_comb(
    const __half* __restrict__ o16, const __half* __restrict__ wowl,
    float* __restrict__ P)
{
    int si = blockIdx.z;
    int M = c_Ms[si];
    int bM = blockIdx.y * 64;
    if (bM >= M) return;
    gemm_core(o16 + (size_t)c_ro[si] * QKVD, wowl + (size_t)si * DMODEL * QKVD,
              nullptr, P + (size_t)si * NPATCH * DMODEL, nullptr,
              M, DMODEL, QKVD, QKVD, 0, QKVD, bM, blockIdx.x * 64, 0, 0, DMODEL);
}

// ffn1: h16 @ W1t + b1 -> gelu -> ff16
__global__ void __launch_bounds__(256) gemm_ffn1(
    const __half* __restrict__ h16, const __half* __restrict__ W1t,
    const float* __restrict__ b1, __half* __restrict__ ff16)
{
    int bM = blockIdx.y * 64;
    if (bM >= NPATCH) return;
    gemm_core(h16, W1t, b1, nullptr, ff16, NPATCH, FFD, DMODEL, DMODEL, 0, DMODEL,
              bM, blockIdx.x * 64, 1, 1, FFD);
}

// ffn2 split-K 4: z chunks of 512 over K=2048
__global__ void __launch_bounds__(256) gemm_ffn2(
    const __half* __restrict__ ff16, const __half* __restrict__ W2t,
    float* __restrict__ part)
{
    int bM = blockIdx.y * 64;
    if (bM >= NPATCH) return;
    int z = blockIdx.z;
    gemm_core(ff16, W2t, nullptr, part + (size_t)z * NPATCH * DMODEL, nullptr,
              NPATCH, DMODEL, FFD, FFD, z * 512, 512, bM, blockIdx.x * 64, 0, 0, DMODEL);
}

// ---------------- small kernels ----------------
__global__ void colsum_kernel(const float* __restrict__ W, float* __restrict__ cs) {
    int d = threadIdx.x;
    float s0 = 0.f, s1 = 0.f, s2 = 0.f, s3 = 0.f;
    #pragma unroll
    for (int p = 0; p < 100; p += 4) {
        s0 += W[(p + 0) * DMODEL + d];
        s1 += W[(p + 1) * DMODEL + d];
        s2 += W[(p + 2) * DMODEL + d];
        s3 += W[(p + 3) * DMODEL + d];
    }
    cs[d] = (s0 + s1) + (s2 + s3);
}

__global__ void init_h_kernel(const float* __restrict__ cs, const float* __restrict__ ln_in_b,
                              const float* __restrict__ patch_b, const float* __restrict__ pos,
                              float* __restrict__ h, __half* __restrict__ h16) {
    int n = blockIdx.x, d = threadIdx.x;
    float v = ln_in_b[0] * cs[d] + patch_b[d] + pos[n * DMODEL + d];
    h[n * DMODEL + d] = v;
    h16[n * DMODEL + d] = __float2half_rn(v);
}

__global__ void pool_kernel(const float* __restrict__ h, __half* __restrict__ p16) {
    int i = blockIdx.x, d = threadIdx.x;
    float v;
    if (i < 250) {
        v = 0.5f * (h[(2 * i) * DMODEL + d] + h[(2 * i + 1) * DMODEL + d]);
    } else {
        int j = i - 250;
        v = 0.25f * (h[(4 * j) * DMODEL + d] + h[(4 * j + 1) * DMODEL + d] +
                     h[(4 * j + 2) * DMODEL + d] + h[(4 * j + 3) * DMODEL + d]);
    }
    p16[i * DMODEL + d] = __float2half_rn(v);
}

// ---------------- attention (fp32 in, fp16 out) ----------------
__global__ void __launch_bounds__(256) attn_kernel(
    const float* __restrict__ q, const float* __restrict__ k,
    const float* __restrict__ v, __half* __restrict__ o16)
{
    __shared__ float Ks[32][34];
    __shared__ float Vs[32][34];
    __shared__ float OS[8][32][34];

    const int b = blockIdx.x;
    int Ns, ro, h, qg;
    if (b < 315)      { Ns = 500; ro = 0;   h = b / 63;  qg = b % 63; }
    else if (b < 475) { int c = b - 315; Ns = 250; ro = 500; h = c / 32; qg = c % 32; }
    else              { int c = b - 475; Ns = 125; ro = 750; h = c / 16; qg = c % 16; }

    const int wid = threadIdx.x >> 5;
    const int lane = threadIdx.x & 31;
    const int n = qg * 8 + wid;
    const bool valid = n < Ns;
    const int nq = valid ? n : (Ns - 1);
    const float scale = 0.1767766952966369f;

    float2 qr[16];
    {
        const float2* qp = (const float2*)(q + (size_t)(ro + nq) * QKVD + h * KDIM);
        #pragma unroll
        for (int i = 0; i < 16; i++) {
            float2 tq = qp[i];
            qr[i] = make_float2(tq.x * scale, tq.y * scale);
        }
    }

    float mmax = -INFINITY, ssum = 0.f;
    float oa[32];
    #pragma unroll
    for (int d = 0; d < 32; d++) oa[d] = 0.f;

    const int nt = (Ns + 31) >> 5;
    for (int tt = 0; tt < nt; tt++) {
        const int kt = tt << 5;
        {
            const int m = threadIdx.x >> 3;
            const int dq = (threadIdx.x & 7) << 2;
            const int row = min(kt + m, Ns - 1);
            const float4 kk = *(const float4*)(k + (size_t)(ro + row) * QKVD + h * KDIM + dq);
            const float4 vv = *(const float4*)(v + (size_t)(ro + row) * QKVD + h * KDIM + dq);
            *(float2*)&Ks[m][dq]     = make_float2(kk.x, kk.y);
            *(float2*)&Ks[m][dq + 2] = make_float2(kk.z, kk.w);
            *(float2*)&Vs[m][dq]     = make_float2(vv.x, vv.y);
            *(float2*)&Vs[m][dq + 2] = make_float2(vv.z, vv.w);
        }
        __syncthreads();

        float s0 = 0.f, s1 = 0.f;
        #pragma unroll
        for (int i = 0; i < 16; i++) {
            float2 kk = *(const float2*)&Ks[lane][2 * i];
            s0 = fmaf(qr[i].x, kk.x, s0);
            s1 = fmaf(qr[i].y, kk.y, s1);
        }
        float s = s0 + s1;
        if (kt + lane >= Ns) s = -INFINITY;

        float nm = fmaxf(mmax, s);
        float corr = __expf(mmax - nm);
        float p = __expf(s - nm);
        ssum = ssum * corr + p;
        #pragma unroll
        for (int i = 0; i < 16; i++) {
            float2 vv = *(const float2*)&Vs[lane][2 * i];
            oa[2 * i]     = oa[2 * i]     * corr + p * vv.x;
            oa[2 * i + 1] = oa[2 * i + 1] * corr + p * vv.y;
        }
        mmax = nm;
        __syncthreads();
    }

    float gm = mmax;
    #pragma unroll
    for (int off = 16; off; off >>= 1) gm = fmaxf(gm, __shfl_xor_sync(0xffffffffu, gm, off));
    float c = __expf(mmax - gm);
    float ss = ssum * c;
    #pragma unroll
    for (int off = 16; off; off >>= 1) ss += __shfl_xor_sync(0xffffffffu, ss, off);

    #pragma unroll
    for (int i = 0; i < 16; i++)
        *(float2*)&OS[wid][lane][2 * i] = make_float2(oa[2 * i] * c, oa[2 * i + 1] * c);
    __syncwarp();

    float accd = 0.f;
    #pragma unroll
    for (int m = 0; m < 32; m++) accd += OS[wid][m][lane];
    if (valid)
        o16[(size_t)(ro + n) * QKVD + h * KDIM + lane] = __float2half_rn(accd / ss);
}

// LN finish: write fp32 h and fp16 h16
__device__ __forceinline__ void ln_finish(float v0, float v1, int n, int t,
                                          float* red, float* statp,
                                          float* __restrict__ h, __half* __restrict__ h16,
                                          const float* __restrict__ g,
                                          const float* __restrict__ b) {
    float s = v0 + v1;
    #pragma unroll
    for (int o = 16; o; o >>= 1) s += __shfl_xor_sync(0xffffffffu, s, o);
    if ((t & 31) == 0) red[t >> 5] = s;
    __syncthreads();
    if (t < 32) {
        float x = (t < 8) ? red[t] : 0.f;
        #pragma unroll
        for (int o = 4; o; o >>= 1) x += __shfl_xor_sync(0xffffffffu, x, o);
        if (t == 0) *statp = x / (float)DMODEL;
    }
    __syncthreads();
    float mean = *statp;
    float dd0 = v0 - mean, dd1 = v1 - mean;
    __syncthreads();
    float vs = dd0 * dd0 + dd1 * dd1;
    #pragma unroll
    for (int o = 16; o; o >>= 1) vs += __shfl_xor_sync(0xffffffffu, vs, o);
    if ((t & 31) == 0) red[t >> 5] = vs;
    __syncthreads();
    if (t < 32) {
        float x = (t < 8) ? red[t] : 0.f;
        #pragma unroll
        for (int o = 4; o; o >>= 1) x += __shfl_xor_sync(0xffffffffu, x, o);
        if (t == 0) *statp = rsqrtf(x / (float)DMODEL + LN_EPS);
    }
    __syncthreads();
    float rstd = *statp;
    float o0 = dd0 * rstd * g[t] + b[t];
    float o1 = dd1 * rstd * g[t + 256] + b[t + 256];
    h[n * DMODEL + t] = o0;
    h[n * DMODEL + t + 256] = o1;
    h16[n * DMODEL + t] = __float2half_rn(o0);
    h16[n * DMODEL + t + 256] = __float2half_rn(o1);
}

// comb partials (3 scales, upsampled) + bcomb biases + residual + LN
__global__ void reduce_comb_ln(const float* __restrict__ P,
                               const float* __restrict__ bias,
                               const float* __restrict__ bcl,   // bcomb + l*3*512
                               float* __restrict__ h, __half* __restrict__ h16,
                               const float* __restrict__ g,
                               const float* __restrict__ b) {
    int n = blockIdx.x, t = threadIdx.x;
    __shared__ float red[8];
    __shared__ float stat;
    const size_t ND = (size_t)NPATCH * DMODEL;
    const int n2 = n >> 1, n4 = n >> 2;
    float bsum0 = bias[t] + bcl[t] + bcl[DMODEL + t] + bcl[2 * DMODEL + t];
    float bsum1 = bias[t + 256] + bcl[t + 256] + bcl[DMODEL + t + 256]
                + bcl[2 * DMODEL + t + 256];
    float v0 = h[n * DMODEL + t]       + bsum0;
    float v1 = h[n * DMODEL + t + 256] + bsum1;
    v0 += P[0 * ND + (size_t)n  * DMODEL + t];
    v1 += P[0 * ND + (size_t)n  * DMODEL + t + 256];
    v0 += P[1 * ND + (size_t)n2 * DMODEL + t];
    v1 += P[1 * ND + (size_t)n2 * DMODEL + t + 256];
    v0 += P[2 * ND + (size_t)n4 * DMODEL + t];
    v1 += P[2 * ND + (size_t)n4 * DMODEL + t + 256];
    ln_finish(v0, v1, n, t, red, &stat, h, h16, g, b);
}

// ffn2 partials + residual + LN
__global__ void reduce_add_ln(const float* __restrict__ part, int S,
                              const float* __restrict__ bias,
                              float* __restrict__ h, __half* __restrict__ h16,
                              const float* __restrict__ g,
                              const float* __restrict__ b) {
    int n = blockIdx.x, t = threadIdx.x;
    __shared__ float red[8];
    __shared__ float stat;
    float v0 = h[n * DMODEL + t]       + bias[t];
    float v1 = h[n * DMODEL + t + 256] + bias[t + 256];
    for (int s = 0; s < S; s++) {
        v0 += part[(size_t)s * NPATCH * DMODEL + n * DMODEL + t];
        v1 += part[(size_t)s * NPATCH * DMODEL + n * DMODEL + t + 256];
    }
    ln_finish(v0, v1, n, t, red, &stat, h, h16, g, b);
}

// fused global-mean-pool + head + softmax + broadcast
__global__ void head_kernel(const float* __restrict__ h, const float* __restrict__ W,
                            const float* __restrict__ b, float* __restrict__ out) {
    __shared__ float gs[DMODEL];
    __shared__ float red[8];
    __shared__ float stat;
    int t = threadIdx.x;
    {
        float s0 = 0.f, s1 = 0.f;
        #pragma unroll 10
        for (int n = 0; n < NPATCH; n++) {
            s0 += h[n * DMODEL + t];
            s1 += h[n * DMODEL + t + 256];
        }
        gs[t] = s0 / (float)NPATCH;
        gs[t + 256] = s1 / (float)NPATCH;
    }
    __syncthreads();
    float acc = b[t];
    #pragma unroll 8
    for (int d = 0; d < DMODEL; d++) acc += gs[d] * W[d * NCLS + t];

    float m = acc;
    #pragma unroll
    for (int o = 16; o; o >>= 1) m = fmaxf(m, __shfl_xor_sync(0xffffffffu, m, o));
    if ((t & 31) == 0) red[t >> 5] = m;
    __syncthreads();
    if (t < 32) {
        float x = (t < 8) ? red[t] : -INFINITY;
        #pragma unroll
        for (int o = 4; o; o >>= 1) x = fmaxf(x, __shfl_xor_sync(0xffffffffu, x, o));
        if (t == 0) stat = x;
    }
    __syncthreads();
    float e = expf(acc - stat);
    __syncthreads();
    float s = e;
    #pragma unroll
    for (int o = 16; o; o >>= 1) s += __shfl_xor_sync(0xffffffffu, s, o);
    if ((t & 31) == 0) red[t >> 5] = s;
    __syncthreads();
    if (t < 32) {
        float x = (t < 8) ? red[t] : 0.f;
        #pragma unroll
        for (int o = 4; o; o >>= 1) x += __shfl_xor_sync(0xffffffffu, x, o);
        if (t == 0) stat = x;
    }
    __syncthreads();
    float p = e / stat;
    for (int bb = 0; bb < NBATCH; bb++) out[bb * NCLS + t] = p;
}

// ---------------- host launcher ----------------
extern "C" void kernel_launch(void* const* d_in, const int* in_sizes, int n_in,
                              void* d_out, int out_size) {
    const float* ln_in_b = (const float*)d_in[2];
    const float* patch_W = (const float*)d_in[3];
    const float* patch_b = (const float*)d_in[4];
    const float* pos_emb = (const float*)d_in[5];
    const float* Wq = (const float*)d_in[6];
    const float* bq = (const float*)d_in[7];
    const float* Wk = (const float*)d_in[8];
    const float* bk = (const float*)d_in[9];
    const float* Wv = (const float*)d_in[10];
    const float* bv = (const float*)d_in[11];
    const float* Wo = (const float*)d_in[12];
    const float* bo = (const float*)d_in[13];
    const float* Wc = (const float*)d_in[14];
    const float* bc = (const float*)d_in[15];
    const float* ln1_g = (const float*)d_in[16];
    const float* ln1_b = (const float*)d_in[17];
    const float* W1 = (const float*)d_in[18];
    const float* b1 = (const float*)d_in[19];
    const float* W2 = (const float*)d_in[20];
    const float* b2 = (const float*)d_in[21];
    const float* ln2_g = (const float*)d_in[22];
    const float* ln2_b = (const float*)d_in[23];
    const float* head_W = (const float*)d_in[24];
    const float* head_b = (const float*)d_in[25];
    float* out = (float*)d_out;

    float *hp, *qp, *kp, *vp, *partp, *csp, *bcombp;
    __half *h16p, *pool16p, *o16p, *ff16p;
    __half *wq16, *wk16, *wv16, *wo16n, *wc16, *wow16, *w116, *w216;
    cudaGetSymbolAddress((void**)&hp,  d_h);
    cudaGetSymbolAddress((void**)&h16p, d_h16);
    cudaGetSymbolAddress((void**)&pool16p, d_pool16);
    cudaGetSymbolAddress((void**)&qp,  d_q);
    cudaGetSymbolAddress((void**)&kp,  d_k);
    cudaGetSymbolAddress((void**)&vp,  d_v);
    cudaGetSymbolAddress((void**)&o16p, d_o16);
    cudaGetSymbolAddress((void**)&ff16p, d_ff16);
    cudaGetSymbolAddress((void**)&partp, d_part);
    cudaGetSymbolAddress((void**)&csp, d_cs);
    cudaGetSymbolAddress((void**)&bcombp, d_bcomb);
    cudaGetSymbolAddress((void**)&wq16, d_Wq16);
    cudaGetSymbolAddress((void**)&wk16, d_Wk16);
    cudaGetSymbolAddress((void**)&wv16, d_Wv16);
    cudaGetSymbolAddress((void**)&wo16n, d_Wo16n);
    cudaGetSymbolAddress((void**)&wc16, d_Wc16);
    cudaGetSymbolAddress((void**)&wow16, d_Wow16);
    cudaGetSymbolAddress((void**)&w116, d_W116);
    cudaGetSymbolAddress((void**)&w216, d_W216);

    // batched transpose/convert: 7 segments in one launch
    TCParams P;
    int base = 0;
    auto seg = [&](int i, const float* s, __half* d, int K, int N, int nb, int notrans) {
        P.s[i].src = s; P.s[i].dst = d; P.s[i].K = K; P.s[i].N = N;
        P.s[i].nx = N / 32; P.s[i].ny = K / 32; P.s[i].base = base; P.s[i].notrans = notrans;
        base += (N / 32) * (K / 32) * nb;
    };
    seg(0, Wq, wq16, DMODEL, QKVD, 18, 0);
    seg(1, Wk, wk16, DMODEL, QKVD, 18, 0);
    seg(2, Wv, wv16, DMODEL, QKVD, 18, 0);
    seg(3, Wc, wc16, DMODEL, DMODEL, 18, 0);
    seg(4, W1, w116, DMODEL, FFD, 6, 0);
    seg(5, W2, w216, FFD, DMODEL, 6, 0);
    seg(6, Wo, wo16n, QKVD, DMODEL, 18, 1);

    dim3 tb(32, 8);
    transconv_all<<<base, tb>>>(P);
    gemm_wow<<<dim3(3, 8, 18), 256, SMEMB>>>(wc16, wo16n, wow16);
    bcomb_kernel<<<18, DMODEL>>>(Wc, bo, bcombp);
    colsum_kernel<<<1, DMODEL>>>(patch_W, csp);
    init_h_kernel<<<NPATCH, DMODEL>>>(csp, ln_in_b, patch_b, pos_emb, hp, h16p);

    for (int l = 0; l < NLAYER; l++) {
        size_t bqkv = (size_t)l * 3 * QKVD;

        pool_kernel<<<375, DMODEL>>>(hp, pool16p);
        gemm_qkv<<<dim3(3, 8, 9), 256, SMEMB>>>(h16p, pool16p,
            wq16 + (size_t)l * 3 * QKVD * DMODEL,
            wk16 + (size_t)l * 3 * QKVD * DMODEL,
            wv16 + (size_t)l * 3 * QKVD * DMODEL,
            bq + bqkv, bk + bqkv, bv + bqkv, qp, kp, vp);
        attn_kernel<<<555, 256>>>(qp, kp, vp, o16p);

        gemm_comb<<<dim3(8, 8, 3), 256, SMEMB>>>(o16p,
            wow16 + (size_t)l * 3 * DMODEL * QKVD, partp);
        reduce_comb_ln<<<NPATCH, 256>>>(partp, bc + (size_t)l * DMODEL,
                                        bcombp + (size_t)l * 3 * DMODEL, hp, h16p,
                                        ln1_g + l * DMODEL, ln1_b + l * DMODEL);

        gemm_ffn1<<<dim3(32, 8), 256, SMEMB>>>(h16p,
            w116 + (size_t)l * FFD * DMODEL, b1 + (size_t)l * FFD, ff16p);
        gemm_ffn2<<<dim3(8, 8, 4), 256, SMEMB>>>(ff16p,
            w216 + (size_t)l * DMODEL * FFD, partp);
        reduce_add_ln<<<NPATCH, 256>>>(partp, 4, b2 + (size_t)l * DMODEL, hp, h16p,
                                       ln2_g + l * DMODEL, ln2_b + l * DMODEL);
    }

    head_kernel<<<1, NCLS>>>(hp, head_W, head_b, out);
}